// round 16
// baseline (speedup 1.0000x reference)
#include <cuda_runtime.h>
#include <cuda_fp16.h>
#include <math.h>

#define T_STEPS 256
#define B_SZ    64
#define H_SZ    1024
#define O_SZ    1024
#define BH      (B_SZ * H_SZ)        // 65536
#define M_TOT   (T_STEPS * B_SZ)     // 16384
#define KSPLIT  8                    // recurrence k-split == cluster size
#define NCTA    128
#define K3P     64                   // persistent K3 worker CTAs
#define PAD     40                   // smem row stride (fp16 elems), big gemms
#define RPAD    136                  // smem row stride (fp16 elems), rec tiles

typedef unsigned long long u64;
typedef unsigned int u32;

__device__ __forceinline__ u32 smem_u32(const void* p) {
    u32 a; asm("{ .reg .u64 t; cvta.to.shared.u64 t, %1; cvt.u32.u64 %0, t; }"
               : "=r"(a) : "l"(p));
    return a;
}

// ---- cp.async helpers ------------------------------------------------------
__device__ __forceinline__ void cp16(u32 dst, const void* src) {
    asm volatile("cp.async.cg.shared.global [%0], [%1], 16;"
                 :: "r"(dst), "l"(src));
}
#define CP_COMMIT() asm volatile("cp.async.commit_group;" ::: "memory")
#define CP_WAIT0()  asm volatile("cp.async.wait_group 0;" ::: "memory")

// ---- mma.sync helpers ------------------------------------------------------
__device__ __forceinline__ void ldmx4(u32& r0, u32& r1, u32& r2, u32& r3, u32 a) {
    asm volatile("ldmatrix.sync.aligned.m8n8.x4.shared.b16 {%0,%1,%2,%3}, [%4];"
                 : "=r"(r0), "=r"(r1), "=r"(r2), "=r"(r3) : "r"(a));
}
__device__ __forceinline__ void mma_f16(float* c, const u32* a, const u32* b) {
    asm volatile(
        "mma.sync.aligned.m16n8k16.row.col.f32.f16.f16.f32 "
        "{%0,%1,%2,%3}, {%4,%5,%6,%7}, {%8,%9}, {%0,%1,%2,%3};"
        : "+f"(c[0]), "+f"(c[1]), "+f"(c[2]), "+f"(c[3])
        : "r"(a[0]), "r"(a[1]), "r"(a[2]), "r"(a[3]), "r"(b[0]), "r"(b[1]));
}

// ---- scratch ---------------------------------------------------------------
__device__ float g_acc[(size_t)M_TOT * H_SZ];      // ix + bi + bh (fp32)
__device__ __half g_A1f[(size_t)M_TOT * H_SZ];     // gathered emb, single fp16
__device__ __half g_hsf[(size_t)M_TOT * H_SZ];     // h states, single fp16
__device__ __half g_h0f[BH];
__device__ __half g_WiThf[(size_t)H_SZ * H_SZ];    // fp16 hi/lo [n][k]
__device__ __half g_WiTlf[(size_t)H_SZ * H_SZ];
__device__ __half g_WoThf[(size_t)H_SZ * O_SZ];
__device__ __half g_WoTlf[(size_t)H_SZ * O_SZ];
__device__ __half g_WhThf[(size_t)H_SZ * H_SZ];
__device__ __half g_WhTlf[(size_t)H_SZ * H_SZ];
__device__ float g_parts[2][(size_t)KSPLIT * BH];  // double-buffered by t&1
__device__ float g_bias1[H_SZ];
__device__ u32 g_stepf[16][8];                     // rec per-(chunk, kc) flags
__device__ u32 g_acc_cnt[128];                     // per-mt K1 completion (8 = done)
__device__ u32 g_k3_next;                          // K3 dynamic tile counter

// ---------------------------------------------------------------------------
// Prep kernels
// ---------------------------------------------------------------------------
__global__ void prep_bias(const float* __restrict__ bi, const float* __restrict__ bh) {
    int i = blockIdx.x * 256 + threadIdx.x;
    g_bias1[i] = bi[i] + bh[i];
}

// W=0: Wi, W=1: Wo, W=2: Wh -> fp16 hi/lo [n][k]
template<int W>
__global__ void prep_transpose_f16(const float* __restrict__ src) {
    __shared__ float ts[32][33];
    __half* dhi = (W == 0) ? g_WiThf : (W == 1) ? g_WoThf : g_WhThf;
    __half* dlo = (W == 0) ? g_WiTlf : (W == 1) ? g_WoTlf : g_WhTlf;
    int n0 = blockIdx.x * 32, k0 = blockIdx.y * 32;
    int tx = threadIdx.x & 31, ty = threadIdx.x >> 5;
#pragma unroll
    for (int i = 0; i < 4; i++)
        ts[ty + i * 8][tx] = src[(size_t)(k0 + ty + i * 8) * H_SZ + n0 + tx];
    __syncthreads();
#pragma unroll
    for (int i = 0; i < 4; i++) {
        int n = n0 + ty + i * 8;
        float v = ts[tx][ty + i * 8];
        __half h = __float2half_rn(v);
        float r = v - __half2float(h);
        dhi[(size_t)n * H_SZ + k0 + tx] = h;
        dlo[(size_t)n * H_SZ + k0 + tx] = __float2half_rn(r);
    }
}

__global__ void prep_gather(const int* __restrict__ input, const float* __restrict__ emb) {
    size_t g = (size_t)blockIdx.x * 256 + threadIdx.x;
    size_t e = g * 8;
    int m = (int)(e >> 10), k = (int)(e & 1023);
    int t = m >> 6, b = m & 63;
    int row = input[b * T_STEPS + t];
    float4 v0 = *(const float4*)(emb + (size_t)row * H_SZ + k);
    float4 v1 = *(const float4*)(emb + (size_t)row * H_SZ + k + 4);
    __half hh[8] = {__float2half_rn(v0.x), __float2half_rn(v0.y),
                    __float2half_rn(v0.z), __float2half_rn(v0.w),
                    __float2half_rn(v1.x), __float2half_rn(v1.y),
                    __float2half_rn(v1.z), __float2half_rn(v1.w)};
    *(uint4*)(g_A1f + e) = *(uint4*)hh;
}

__global__ void prep_h0(const float* __restrict__ hidden0) {
    size_t e = ((size_t)blockIdx.x * 256 + threadIdx.x) * 4;
    float4 v = *(const float4*)(hidden0 + e);
    __half hh[4] = {__float2half_rn(v.x), __float2half_rn(v.y),
                    __float2half_rn(v.z), __float2half_rn(v.w)};
    *(uint2*)(g_h0f + e) = *(uint2*)hh;
}

// cleanup: reset all flags after mega (replay safety)
__global__ void cleanup_flags(void) {
    int i = threadIdx.x;
    if (i < 128) ((u32*)g_stepf)[i] = 0;
    else if (i < 256) g_acc_cnt[i - 128] = 0;
    if (i == 0) g_k3_next = 0;
}

// ---------------------------------------------------------------------------
// Shared fp16 2-term GEMM body (proven). MODE 0: K1 (A1f x WiT -> g_acc+bias1)
// MODE 1: K3 (hsf x WoT -> out[b][t] + bo)
// ---------------------------------------------------------------------------
#define TILE_BF (128 * PAD)
#define SMEM_G (2 * 3 * TILE_BF * 2)

template<int MODE>
__device__ __forceinline__ void gemm_body(char* smc, int mt, int nt,
                                          const float* __restrict__ bo,
                                          float* __restrict__ out)
{
    __half* smh = (__half*)smc;
    const int tid = threadIdx.x, wid = tid >> 5, lane = tid & 31;
    const int wm = wid >> 1, wn = wid & 1;

    const __half* A  = MODE ? g_hsf   : g_A1f;
    const __half* Bh = MODE ? g_WoThf : g_WiThf;
    const __half* Bl = MODE ? g_WoTlf : g_WiTlf;
    const float* bias = MODE ? bo : g_bias1;

    const __half* srcT[3] = { A  + (size_t)mt * 128 * H_SZ,
                              Bh + (size_t)nt * 128 * H_SZ,
                              Bl + (size_t)nt * 128 * H_SZ };

    const int r0 = tid >> 2, q0 = tid & 3;
    const int r1 = r0 + 64;
    const u32 sbase = smem_u32(smh);

#pragma unroll
    for (int t4 = 0; t4 < 3; t4++) {
        const __half* s = srcT[t4];
        u32 d = sbase + (u32)(t4 * TILE_BF) * 2;
        cp16(d + (u32)(r0 * PAD + q0 * 8) * 2, s + (size_t)r0 * H_SZ + q0 * 8);
        cp16(d + (u32)(r1 * PAD + q0 * 8) * 2, s + (size_t)r1 * H_SZ + q0 * 8);
    }
    CP_COMMIT(); CP_WAIT0();
    __syncthreads();

    float acc[2][8][4];
#pragma unroll
    for (int mi = 0; mi < 2; mi++)
#pragma unroll
        for (int j = 0; j < 8; j++)
#pragma unroll
            for (int v = 0; v < 4; v++) acc[mi][j][v] = 0.f;

    const int a_row = lane & 15, a_kq = lane >> 4;
    const int b_nr = (lane >> 4) * 8 + (lane & 7), b_kq = (lane >> 3) & 1;

#pragma unroll 1
    for (int c = 0; c < 32; c++) {
        const int buf = c & 1;
        if (c < 31) {
            const int col0 = (c + 1) * 32;
#pragma unroll
            for (int t4 = 0; t4 < 3; t4++) {
                const __half* s = srcT[t4] + col0;
                u32 d = sbase + (u32)(((buf ^ 1) * 3 + t4) * TILE_BF) * 2;
                cp16(d + (u32)(r0 * PAD + q0 * 8) * 2, s + (size_t)r0 * H_SZ + q0 * 8);
                cp16(d + (u32)(r1 * PAD + q0 * 8) * 2, s + (size_t)r1 * H_SZ + q0 * 8);
            }
            CP_COMMIT();
        }

        const u32 bA = sbase + (u32)(buf * 3) * TILE_BF * 2;
#pragma unroll
        for (int s = 0; s < 2; s++) {
            const int kc0 = s * 16;
            u32 a[2][4], bhi[8][2], blo[8][2];
#pragma unroll
            for (int mi = 0; mi < 2; mi++) {
                u32 off = (u32)((wm * 32 + mi * 16 + a_row) * PAD + kc0 + a_kq * 8) * 2;
                ldmx4(a[mi][0], a[mi][1], a[mi][2], a[mi][3], bA + 0 * TILE_BF * 2 + off);
            }
#pragma unroll
            for (int ni = 0; ni < 4; ni++) {
                u32 off = (u32)((wn * 64 + ni * 16 + b_nr) * PAD + kc0 + b_kq * 8) * 2;
                ldmx4(bhi[2*ni][0], bhi[2*ni][1], bhi[2*ni+1][0], bhi[2*ni+1][1],
                      bA + 1 * TILE_BF * 2 + off);
                ldmx4(blo[2*ni][0], blo[2*ni][1], blo[2*ni+1][0], blo[2*ni+1][1],
                      bA + 2 * TILE_BF * 2 + off);
            }
#pragma unroll
            for (int mi = 0; mi < 2; mi++)
#pragma unroll
                for (int j = 0; j < 8; j++) {
                    mma_f16(acc[mi][j], a[mi], bhi[j]);
                    mma_f16(acc[mi][j], a[mi], blo[j]);
                }
        }
        if (c < 31) CP_WAIT0();
        __syncthreads();
    }

    const int gid = lane >> 2, qid = lane & 3;
#pragma unroll
    for (int mi = 0; mi < 2; mi++) {
#pragma unroll
        for (int j = 0; j < 8; j++) {
            int col = nt * 128 + wn * 64 + j * 8 + qid * 2;
            float2 bv = *(const float2*)(bias + col);
            int mA = mt * 128 + wm * 32 + mi * 16 + gid;
            int mB = mA + 8;
            float* dA; float* dB;
            if (MODE == 0) {
                dA = g_acc + (size_t)mA * H_SZ + col;
                dB = g_acc + (size_t)mB * H_SZ + col;
            } else {
                dA = out + ((size_t)(mA & 63) * T_STEPS + (mA >> 6)) * O_SZ + col;
                dB = out + ((size_t)(mB & 63) * T_STEPS + (mB >> 6)) * O_SZ + col;
            }
            *(float2*)dA = make_float2(acc[mi][j][0] + bv.x, acc[mi][j][1] + bv.y);
            *(float2*)dB = make_float2(acc[mi][j][2] + bv.x, acc[mi][j][3] + bv.y);
        }
    }

    if (MODE == 0) {
        // publish this acc tile
        __threadfence();
        __syncthreads();
        if (tid == 0) atomicAdd(&g_acc_cnt[mt], 1u);
    }
}

// ---------------------------------------------------------------------------
// Recurrence body (R13-proven)
// ---------------------------------------------------------------------------
#define R_WHI 0
#define R_WLO (64 * RPAD)
#define R_A   (2 * 64 * RPAD)
#define SMEM_REC_BYTES (3 * 64 * RPAD * 2)
#define SMEM_MEGA (SMEM_G > SMEM_REC_BYTES ? SMEM_G : SMEM_REC_BYTES)

__device__ __forceinline__ void rec_body(char* rsm_c, float* __restrict__ hid_out)
{
    __half* rsh = (__half*)rsm_c;
    const int tid = threadIdx.x, wid = tid >> 5, lane = tid & 31;
    const int ct  = blockIdx.x >> 3;
    const int kc  = blockIdx.x & 7;
    const int wm  = wid >> 1, wn = wid & 1;

    // one-time Wh tile load: rows n = ct*64 .. +64, cols k = kc*128 .. +128
    {
        const size_t base = (size_t)(ct * 64) * H_SZ + kc * 128;
#pragma unroll
        for (int i = 0; i < 4; i++) {
            int ch = tid + i * 256;
            int r  = ch >> 4;
            int co = (ch & 15) * 8;
            *(uint4*)(rsh + R_WHI + r * RPAD + co) =
                *(const uint4*)(g_WhThf + base + (size_t)r * H_SZ + co);
            *(uint4*)(rsh + R_WLO + r * RPAD + co) =
                *(const uint4*)(g_WhTlf + base + (size_t)r * H_SZ + co);
        }
    }

    const u32 sbase = smem_u32(rsh);
    const int a_row = lane & 15, a_kq = lane >> 4;
    const int b_nr = (lane >> 4) * 8 + (lane & 7), b_kq = (lane >> 3) & 1;
    const int gid = lane >> 2, qid = lane & 3;

    const int red_row = kc * 8 + (tid >> 5);
    const size_t red_off = (size_t)red_row * H_SZ + ct * 64 + (tid & 31) * 2;

    volatile u32* myflag = (tid < 16)
        ? &g_stepf[2 * kc + (tid >> 3)][tid & 7] : (volatile u32*)0;

#pragma unroll 1
    for (int t = 0; t < T_STEPS; t++) {
        const __half* hsrc = t ? (g_hsf + (size_t)(t - 1) * BH) : g_h0f;
        float* parts = g_parts[t & 1];

        // wait producers: K1 acc tile for this t, and h flags (t>0)
        if (tid == 0) {
            volatile u32* ac = &g_acc_cnt[t >> 1];
            while (*ac < 8u) { }
            __threadfence();
        }
        if (t > 0 && tid < 16) {
            while (*myflag < (u32)t) { }
            __threadfence();
        }
        __syncthreads();

        float2 aacc = __ldcg((const float2*)(g_acc + (size_t)t * BH + red_off));

        // stage h slice (64 x 128 fp16 = 16KB) via cp.async
#pragma unroll
        for (int i = 0; i < 4; i++) {
            int ch = tid + i * 256;
            int r  = ch >> 4;
            int co = (ch & 15) * 8;
            cp16(sbase + (u32)(R_A + r * RPAD + co) * 2,
                 hsrc + (size_t)r * H_SZ + kc * 128 + co);
        }
        CP_COMMIT(); CP_WAIT0();
        __syncthreads();

        float acc[4][4];
#pragma unroll
        for (int j = 0; j < 4; j++)
#pragma unroll
            for (int v = 0; v < 4; v++) acc[j][v] = 0.f;

#pragma unroll
        for (int ks = 0; ks < 8; ks++) {
            const int k0 = ks * 16;
            u32 a[4], bhi[4][2], blo[4][2];
            {
                u32 off = (u32)((wm * 16 + a_row) * RPAD + k0 + a_kq * 8) * 2;
                ldmx4(a[0], a[1], a[2], a[3], sbase + R_A * 2 + off);
            }
#pragma unroll
            for (int ni = 0; ni < 2; ni++) {
                u32 off = (u32)((wn * 32 + ni * 16 + b_nr) * RPAD + k0 + b_kq * 8) * 2;
                ldmx4(bhi[2*ni][0], bhi[2*ni][1], bhi[2*ni+1][0], bhi[2*ni+1][1],
                      sbase + R_WHI * 2 + off);
                ldmx4(blo[2*ni][0], blo[2*ni][1], blo[2*ni+1][0], blo[2*ni+1][1],
                      sbase + R_WLO * 2 + off);
            }
#pragma unroll
            for (int j = 0; j < 4; j++) {
                mma_f16(acc[j], a, bhi[j]);
                mma_f16(acc[j], a, blo[j]);
            }
        }

        // partial store
        {
            float* p0 = parts + (size_t)kc * BH
                      + (size_t)(wm * 16 + gid) * H_SZ + ct * 64 + wn * 32;
            float* p1 = p0 + 8 * H_SZ;
#pragma unroll
            for (int j = 0; j < 4; j++) {
                *(float2*)(p0 + j * 8 + qid * 2) = make_float2(acc[j][0], acc[j][1]);
                *(float2*)(p1 + j * 8 + qid * 2) = make_float2(acc[j][2], acc[j][3]);
            }
        }

        __threadfence();
        asm volatile("barrier.cluster.arrive.aligned;" ::: "memory");
        asm volatile("barrier.cluster.wait.aligned;"   ::: "memory");

        // in-cluster reduce + tanh + fp16 store
        {
            float2 a2 = aacc;
#pragma unroll
            for (int p = 0; p < KSPLIT; p++) {
                float2 q = __ldcg((const float2*)(parts + (size_t)p * BH + red_off));
                a2.x += q.x; a2.y += q.y;
            }
            a2.x = tanhf(a2.x); a2.y = tanhf(a2.y);

            __half h0 = __float2half_rn(a2.x), h1 = __float2half_rn(a2.y);
            u32 packed = (u32)__half_as_ushort(h0) | ((u32)__half_as_ushort(h1) << 16);
            *(u32*)(g_hsf + (size_t)t * BH + red_off) = packed;

            if (hid_out && t == T_STEPS - 1)
                *(float2*)(hid_out + red_off) = a2;
        }

        __threadfence();
        __syncthreads();
        if (tid == 0)
            *(volatile u32*)&g_stepf[ct][kc] = (u32)(t + 1);
    }
}

// ---------------------------------------------------------------------------
// MEGA: blocks 0..127 rec, 128..1151 K1 tiles, 1152..1215 persistent K3
// workers that dynamically claim tiles via g_k3_next. Workers are dispatched
// LAST -> become resident as K1 retires, when many tiles are already ready.
// ---------------------------------------------------------------------------
__global__ __launch_bounds__(256, 2) __cluster_dims__(KSPLIT, 1, 1)
void mega(float* __restrict__ hid_out, const float* __restrict__ bo,
          float* __restrict__ out)
{
    extern __shared__ char msm[];
    if (blockIdx.x < NCTA) { rec_body(msm, hid_out); return; }
    if (blockIdx.x < NCTA + 1024) {
        int idx = blockIdx.x - NCTA;
        gemm_body<0>(msm, idx >> 3, idx & 7, (const float*)0, (float*)0);
        return;
    }

    // persistent K3 worker
    __shared__ int s_idx;
    const int tid = threadIdx.x;
    for (;;) {
        __syncthreads();                 // protect s_idx from previous iter
        if (tid == 0) s_idx = (int)atomicAdd(&g_k3_next, 1u);
        __syncthreads();
        int idx = s_idx;
        if (idx >= 1024) break;
        int mt = idx >> 3, nt = idx & 7;
        // wait until h(2mt), h(2mt+1) complete across all 128 rec CTAs
        if (tid < 128) {
            volatile u32* f = &((u32*)g_stepf)[tid];
            u32 need = (u32)(2 * mt + 2);
            if (*f < need) {
                u32 ns = 1000;
                while (*f < need) {
                    __nanosleep(ns);
                    if (ns < 4000) ns += ns;
                }
            }
            __threadfence();
        }
        __syncthreads();
        gemm_body<1>(msm, mt, nt, bo, out);
    }
}

// ---------------------------------------------------------------------------
extern "C" void kernel_launch(void* const* d_in, const int* in_sizes, int n_in,
                              void* d_out, int out_size)
{
    const int*   input   = (const int*)  d_in[0];
    const float* hidden0 = (const float*)d_in[1];
    const float* emb     = (const float*)d_in[2];
    const float* Wi      = (const float*)d_in[3];
    const float* bi      = (const float*)d_in[4];
    const float* Wh      = (const float*)d_in[5];
    const float* bh      = (const float*)d_in[6];
    const float* Wo      = (const float*)d_in[7];
    const float* bo      = (const float*)d_in[8];
    float* out = (float*)d_out;

    float* hid_out = (out_size >= M_TOT * O_SZ + BH) ? out + (size_t)M_TOT * O_SZ
                                                     : (float*)0;

    cudaFuncSetAttribute(mega, cudaFuncAttributeMaxDynamicSharedMemorySize, SMEM_MEGA);

    prep_bias<<<4, 256>>>(bi, bh);
    prep_transpose_f16<0><<<dim3(32, 32), 256>>>(Wi);
    prep_transpose_f16<1><<<dim3(32, 32), 256>>>(Wo);
    prep_transpose_f16<2><<<dim3(32, 32), 256>>>(Wh);
    prep_h0<<<64, 256>>>(hidden0);
    prep_gather<<<8192, 256>>>(input, emb);

    mega<<<NCTA + 1024 + K3P, 256, SMEM_MEGA>>>(hid_out, bo, out);
    cleanup_flags<<<1, 256>>>();
}

// round 17
// speedup vs baseline: 1.0593x; 1.0593x over previous
#include <cuda_runtime.h>
#include <cuda_fp16.h>
#include <math.h>

#define T_STEPS 256
#define B_SZ    64
#define H_SZ    1024
#define O_SZ    1024
#define BH      (B_SZ * H_SZ)        // 65536
#define M_TOT   (T_STEPS * B_SZ)     // 16384
#define KSPLIT  8                    // recurrence k-split == cluster size
#define NREC    256                  // rec CTAs (2 per SM on 128 SMs)
#define PAD     40                   // smem row stride (fp16 elems), big gemms
#define RPAD    136                  // smem row stride (fp16 elems), rec tiles

typedef unsigned long long u64;
typedef unsigned int u32;

__device__ __forceinline__ u32 smem_u32(const void* p) {
    u32 a; asm("{ .reg .u64 t; cvta.to.shared.u64 t, %1; cvt.u32.u64 %0, t; }"
               : "=r"(a) : "l"(p));
    return a;
}

// ---- cp.async helpers ------------------------------------------------------
__device__ __forceinline__ void cp16(u32 dst, const void* src) {
    asm volatile("cp.async.cg.shared.global [%0], [%1], 16;"
                 :: "r"(dst), "l"(src));
}
#define CP_COMMIT() asm volatile("cp.async.commit_group;" ::: "memory")
#define CP_WAIT0()  asm volatile("cp.async.wait_group 0;" ::: "memory")

// ---- mma.sync helpers ------------------------------------------------------
__device__ __forceinline__ void ldmx4(u32& r0, u32& r1, u32& r2, u32& r3, u32 a) {
    asm volatile("ldmatrix.sync.aligned.m8n8.x4.shared.b16 {%0,%1,%2,%3}, [%4];"
                 : "=r"(r0), "=r"(r1), "=r"(r2), "=r"(r3) : "r"(a));
}
__device__ __forceinline__ void mma_f16(float* c, const u32* a, const u32* b) {
    asm volatile(
        "mma.sync.aligned.m16n8k16.row.col.f32.f16.f16.f32 "
        "{%0,%1,%2,%3}, {%4,%5,%6,%7}, {%8,%9}, {%0,%1,%2,%3};"
        : "+f"(c[0]), "+f"(c[1]), "+f"(c[2]), "+f"(c[3])
        : "r"(a[0]), "r"(a[1]), "r"(a[2]), "r"(a[3]), "r"(b[0]), "r"(b[1]));
}

// ---- scratch ---------------------------------------------------------------
__device__ float g_acc[(size_t)M_TOT * H_SZ];      // ix + bi + bh (fp32)
__device__ __half g_A1f[(size_t)M_TOT * H_SZ];     // gathered emb, single fp16
__device__ __half g_hsf[(size_t)M_TOT * H_SZ];     // h states, single fp16
__device__ __half g_h0f[BH];
__device__ __half g_WiThf[(size_t)H_SZ * H_SZ];    // fp16 hi/lo [n][k]
__device__ __half g_WiTlf[(size_t)H_SZ * H_SZ];
__device__ __half g_WoThf[(size_t)H_SZ * O_SZ];
__device__ __half g_WoTlf[(size_t)H_SZ * O_SZ];
__device__ __half g_WhThf[(size_t)H_SZ * H_SZ];
__device__ __half g_WhTlf[(size_t)H_SZ * H_SZ];
__device__ float g_parts[2][(size_t)KSPLIT * BH];  // double-buffered by t&1
__device__ float g_bias1[H_SZ];
__device__ unsigned g_cnt[2];
__device__ unsigned g_flag[2];
__device__ u32 g_stepf[32][8];                     // per-(chunk ct, kc) flags
__device__ u32 g_acc_cnt[128];                     // per-mt K1 completion (8 = done)

// ---------------------------------------------------------------------------
// Prep kernels
// ---------------------------------------------------------------------------
__global__ void prep_bias(const float* __restrict__ bi, const float* __restrict__ bh) {
    int i = blockIdx.x * 256 + threadIdx.x;
    g_bias1[i] = bi[i] + bh[i];
}

// W=0: Wi, W=1: Wo, W=2: Wh -> fp16 hi/lo [n][k]
template<int W>
__global__ void prep_transpose_f16(const float* __restrict__ src) {
    __shared__ float ts[32][33];
    __half* dhi = (W == 0) ? g_WiThf : (W == 1) ? g_WoThf : g_WhThf;
    __half* dlo = (W == 0) ? g_WiTlf : (W == 1) ? g_WoTlf : g_WhTlf;
    int n0 = blockIdx.x * 32, k0 = blockIdx.y * 32;
    int tx = threadIdx.x & 31, ty = threadIdx.x >> 5;
#pragma unroll
    for (int i = 0; i < 4; i++)
        ts[ty + i * 8][tx] = src[(size_t)(k0 + ty + i * 8) * H_SZ + n0 + tx];
    __syncthreads();
#pragma unroll
    for (int i = 0; i < 4; i++) {
        int n = n0 + ty + i * 8;
        float v = ts[tx][ty + i * 8];
        __half h = __float2half_rn(v);
        float r = v - __half2float(h);
        dhi[(size_t)n * H_SZ + k0 + tx] = h;
        dlo[(size_t)n * H_SZ + k0 + tx] = __float2half_rn(r);
    }
}

__global__ void prep_gather(const int* __restrict__ input, const float* __restrict__ emb) {
    size_t g = (size_t)blockIdx.x * 256 + threadIdx.x;
    size_t e = g * 8;
    int m = (int)(e >> 10), k = (int)(e & 1023);
    int t = m >> 6, b = m & 63;
    int row = input[b * T_STEPS + t];
    float4 v0 = *(const float4*)(emb + (size_t)row * H_SZ + k);
    float4 v1 = *(const float4*)(emb + (size_t)row * H_SZ + k + 4);
    __half hh[8] = {__float2half_rn(v0.x), __float2half_rn(v0.y),
                    __float2half_rn(v0.z), __float2half_rn(v0.w),
                    __float2half_rn(v1.x), __float2half_rn(v1.y),
                    __float2half_rn(v1.z), __float2half_rn(v1.w)};
    *(uint4*)(g_A1f + e) = *(uint4*)hh;
}

__global__ void prep_h0(const float* __restrict__ hidden0) {
    size_t e = ((size_t)blockIdx.x * 256 + threadIdx.x) * 4;
    float4 v = *(const float4*)(hidden0 + e);
    __half hh[4] = {__float2half_rn(v.x), __float2half_rn(v.y),
                    __float2half_rn(v.z), __float2half_rn(v.w)};
    *(uint2*)(g_h0f + e) = *(uint2*)hh;
}

// ---------------------------------------------------------------------------
// Shared fp16 2-term GEMM body (proven). MODE 0: K1 (A1f x WiT -> g_acc+bias1)
// MODE 1: K3 (hsf x WoT -> out[b][t] + bo)
// ---------------------------------------------------------------------------
#define TILE_BF (128 * PAD)
#define SMEM_G (2 * 3 * TILE_BF * 2)

template<int MODE>
__device__ __forceinline__ void gemm_body(char* smc, int mt, int nt,
                                          const float* __restrict__ bo,
                                          float* __restrict__ out)
{
    __half* smh = (__half*)smc;
    const int tid = threadIdx.x, wid = tid >> 5, lane = tid & 31;
    const int wm = wid >> 1, wn = wid & 1;

    const __half* A  = MODE ? g_hsf   : g_A1f;
    const __half* Bh = MODE ? g_WoThf : g_WiThf;
    const __half* Bl = MODE ? g_WoTlf : g_WiTlf;
    const float* bias = MODE ? bo : g_bias1;

    const __half* srcT[3] = { A  + (size_t)mt * 128 * H_SZ,
                              Bh + (size_t)nt * 128 * H_SZ,
                              Bl + (size_t)nt * 128 * H_SZ };

    const int r0 = tid >> 2, q0 = tid & 3;
    const int r1 = r0 + 64;
    const u32 sbase = smem_u32(smh);

#pragma unroll
    for (int t4 = 0; t4 < 3; t4++) {
        const __half* s = srcT[t4];
        u32 d = sbase + (u32)(t4 * TILE_BF) * 2;
        cp16(d + (u32)(r0 * PAD + q0 * 8) * 2, s + (size_t)r0 * H_SZ + q0 * 8);
        cp16(d + (u32)(r1 * PAD + q0 * 8) * 2, s + (size_t)r1 * H_SZ + q0 * 8);
    }
    CP_COMMIT(); CP_WAIT0();
    __syncthreads();

    float acc[2][8][4];
#pragma unroll
    for (int mi = 0; mi < 2; mi++)
#pragma unroll
        for (int j = 0; j < 8; j++)
#pragma unroll
            for (int v = 0; v < 4; v++) acc[mi][j][v] = 0.f;

    const int a_row = lane & 15, a_kq = lane >> 4;
    const int b_nr = (lane >> 4) * 8 + (lane & 7), b_kq = (lane >> 3) & 1;

#pragma unroll 1
    for (int c = 0; c < 32; c++) {
        const int buf = c & 1;
        if (c < 31) {
            const int col0 = (c + 1) * 32;
#pragma unroll
            for (int t4 = 0; t4 < 3; t4++) {
                const __half* s = srcT[t4] + col0;
                u32 d = sbase + (u32)(((buf ^ 1) * 3 + t4) * TILE_BF) * 2;
                cp16(d + (u32)(r0 * PAD + q0 * 8) * 2, s + (size_t)r0 * H_SZ + q0 * 8);
                cp16(d + (u32)(r1 * PAD + q0 * 8) * 2, s + (size_t)r1 * H_SZ + q0 * 8);
            }
            CP_COMMIT();
        }

        const u32 bA = sbase + (u32)(buf * 3) * TILE_BF * 2;
#pragma unroll
        for (int s = 0; s < 2; s++) {
            const int kc0 = s * 16;
            u32 a[2][4], bhi[8][2], blo[8][2];
#pragma unroll
            for (int mi = 0; mi < 2; mi++) {
                u32 off = (u32)((wm * 32 + mi * 16 + a_row) * PAD + kc0 + a_kq * 8) * 2;
                ldmx4(a[mi][0], a[mi][1], a[mi][2], a[mi][3], bA + 0 * TILE_BF * 2 + off);
            }
#pragma unroll
            for (int ni = 0; ni < 4; ni++) {
                u32 off = (u32)((wn * 64 + ni * 16 + b_nr) * PAD + kc0 + b_kq * 8) * 2;
                ldmx4(bhi[2*ni][0], bhi[2*ni][1], bhi[2*ni+1][0], bhi[2*ni+1][1],
                      bA + 1 * TILE_BF * 2 + off);
                ldmx4(blo[2*ni][0], blo[2*ni][1], blo[2*ni+1][0], blo[2*ni+1][1],
                      bA + 2 * TILE_BF * 2 + off);
            }
#pragma unroll
            for (int mi = 0; mi < 2; mi++)
#pragma unroll
                for (int j = 0; j < 8; j++) {
                    mma_f16(acc[mi][j], a[mi], bhi[j]);
                    mma_f16(acc[mi][j], a[mi], blo[j]);
                }
        }
        if (c < 31) CP_WAIT0();
        __syncthreads();
    }

    const int gid = lane >> 2, qid = lane & 3;
#pragma unroll
    for (int mi = 0; mi < 2; mi++) {
#pragma unroll
        for (int j = 0; j < 8; j++) {
            int col = nt * 128 + wn * 64 + j * 8 + qid * 2;
            float2 bv = *(const float2*)(bias + col);
            int mA = mt * 128 + wm * 32 + mi * 16 + gid;
            int mB = mA + 8;
            float* dA; float* dB;
            if (MODE == 0) {
                dA = g_acc + (size_t)mA * H_SZ + col;
                dB = g_acc + (size_t)mB * H_SZ + col;
            } else {
                dA = out + ((size_t)(mA & 63) * T_STEPS + (mA >> 6)) * O_SZ + col;
                dB = out + ((size_t)(mB & 63) * T_STEPS + (mB >> 6)) * O_SZ + col;
            }
            *(float2*)dA = make_float2(acc[mi][j][0] + bv.x, acc[mi][j][1] + bv.y);
            *(float2*)dB = make_float2(acc[mi][j][2] + bv.x, acc[mi][j][3] + bv.y);
        }
    }

    if (MODE == 0) {
        __threadfence();
        __syncthreads();
        if (tid == 0) atomicAdd(&g_acc_cnt[mt], 1u);
    }
}

// ---------------------------------------------------------------------------
// K3 (serial, proven R13 shape)
// ---------------------------------------------------------------------------
__global__ __launch_bounds__(256) void gemm_out(const float* __restrict__ bo,
                                                float* __restrict__ out)
{
    extern __shared__ char smc[];
    gemm_body<1>(smc, blockIdx.y, blockIdx.x, bo, out);
}

// ---------------------------------------------------------------------------
// Flat grid barrier across the 256 rec CTAs (end-of-rec reset only)
// ---------------------------------------------------------------------------
__device__ __forceinline__ void grid_barrier(int slot) {
    __syncthreads();
    if (threadIdx.x == 0) {
        volatile unsigned* fl = &g_flag[slot];
        unsigned prev = *fl;
        __threadfence();
        unsigned old = atomicAdd(&g_cnt[slot], 1u);
        if (old == NREC - 1) {
            atomicExch(&g_cnt[slot], 0u);
            __threadfence();
            atomicAdd(&g_flag[slot], 1u);
        } else {
            while (*fl == prev) { }
        }
        __threadfence();
    }
    __syncthreads();
}

// ---------------------------------------------------------------------------
// Recurrence: 256 CTAs = 32 ct-chunks (N=32) x 8 kc (K=128). 2 CTAs/SM ->
// two independent pipelines per SM hide each other's latency.
// Wh tile 32x128 hi/lo resident; h 64x128 staged per step; cluster = 8 kc.
// ---------------------------------------------------------------------------
#define R_WHI 0
#define R_WLO (32 * RPAD)
#define R_A   (64 * RPAD)
#define SMEM_REC_BYTES (128 * RPAD * 2)     // 34816
#define SMEM_MEGA (SMEM_G > SMEM_REC_BYTES ? SMEM_G : SMEM_REC_BYTES)

__device__ __forceinline__ void rec_body(char* rsm_c, float* __restrict__ hid_out)
{
    __half* rsh = (__half*)rsm_c;
    const int tid = threadIdx.x, wid = tid >> 5, lane = tid & 31;
    const int ct  = blockIdx.x >> 3;    // 0..31
    const int kc  = blockIdx.x & 7;
    const int wm  = wid >> 1, wn = wid & 1;

    // one-time Wh tile: rows n = ct*32..+32, cols k = kc*128..+128
    {
        const size_t base = (size_t)(ct * 32) * H_SZ + kc * 128;
#pragma unroll
        for (int i = 0; i < 2; i++) {
            int ch = tid + i * 256;     // 0..511
            int r  = ch >> 4;           // 0..31
            int co = (ch & 15) * 8;
            *(uint4*)(rsh + R_WHI + r * RPAD + co) =
                *(const uint4*)(g_WhThf + base + (size_t)r * H_SZ + co);
            *(uint4*)(rsh + R_WLO + r * RPAD + co) =
                *(const uint4*)(g_WhTlf + base + (size_t)r * H_SZ + co);
        }
    }

    const u32 sbase = smem_u32(rsh);
    const int a_row = lane & 15, a_kq = lane >> 4;
    const int b_nr = (lane >> 4) * 8 + (lane & 7), b_kq = (lane >> 3) & 1;
    const int gid = lane >> 2, qid = lane & 3;

    // reduce: row kc*8 + tid>>5, col ct*32 + (tid&31) -- one float per thread
    const int red_row = kc * 8 + (tid >> 5);
    const size_t red_off = (size_t)red_row * H_SZ + ct * 32 + (tid & 31);

    // producers of this CTA's h k-slice: chunks 4kc..4kc+3, subs 0..7
    volatile u32* myflag = (tid < 32)
        ? &g_stepf[4 * kc + (tid >> 3)][tid & 7] : (volatile u32*)0;

#pragma unroll 1
    for (int t = 0; t < T_STEPS; t++) {
        const __half* hsrc = t ? (g_hsf + (size_t)(t - 1) * BH) : g_h0f;
        float* parts = g_parts[t & 1];

        // wait producers: K1 acc tile for this t, and h flags (t>0)
        if (tid == 0) {
            volatile u32* ac = &g_acc_cnt[t >> 1];
            while (*ac < 8u) { }
            __threadfence();
        }
        if (t > 0 && tid < 32) {
            while (*myflag < (u32)t) { }
            __threadfence();
        }
        __syncthreads();

        float aacc = __ldcg(g_acc + (size_t)t * BH + red_off);

        // stage h slice (64 x 128 fp16 = 16KB) via cp.async
#pragma unroll
        for (int i = 0; i < 4; i++) {
            int ch = tid + i * 256;
            int r  = ch >> 4;
            int co = (ch & 15) * 8;
            cp16(sbase + (u32)(R_A + r * RPAD + co) * 2,
                 hsrc + (size_t)r * H_SZ + kc * 128 + co);
        }
        CP_COMMIT(); CP_WAIT0();
        __syncthreads();

        float acc[2][4];
#pragma unroll
        for (int j = 0; j < 2; j++)
#pragma unroll
            for (int v = 0; v < 4; v++) acc[j][v] = 0.f;

#pragma unroll
        for (int ks = 0; ks < 8; ks++) {
            const int k0 = ks * 16;
            u32 a[4], bhi[2][2], blo[2][2];
            {
                u32 off = (u32)((wm * 16 + a_row) * RPAD + k0 + a_kq * 8) * 2;
                ldmx4(a[0], a[1], a[2], a[3], sbase + R_A * 2 + off);
            }
            {
                u32 off = (u32)((wn * 16 + b_nr) * RPAD + k0 + b_kq * 8) * 2;
                ldmx4(bhi[0][0], bhi[0][1], bhi[1][0], bhi[1][1],
                      sbase + R_WHI * 2 + off);
                ldmx4(blo[0][0], blo[0][1], blo[1][0], blo[1][1],
                      sbase + R_WLO * 2 + off);
            }
#pragma unroll
            for (int j = 0; j < 2; j++) {
                mma_f16(acc[j], a, bhi[j]);
                mma_f16(acc[j], a, blo[j]);
            }
        }

        // partial store: rows wm*16+gid(+8), cols ct*32 + wn*16 + j*8 + qid*2
        {
            float* p0 = parts + (size_t)kc * BH
                      + (size_t)(wm * 16 + gid) * H_SZ + ct * 32 + wn * 16;
            float* p1 = p0 + 8 * H_SZ;
#pragma unroll
            for (int j = 0; j < 2; j++) {
                *(float2*)(p0 + j * 8 + qid * 2) = make_float2(acc[j][0], acc[j][1]);
                *(float2*)(p1 + j * 8 + qid * 2) = make_float2(acc[j][2], acc[j][3]);
            }
        }

        __threadfence();
        asm volatile("barrier.cluster.arrive.aligned;" ::: "memory");
        asm volatile("barrier.cluster.wait.aligned;"   ::: "memory");

        // in-cluster reduce + tanh + fp16 store (1 element per thread)
        {
            float a2 = aacc;
#pragma unroll
            for (int p = 0; p < KSPLIT; p++)
                a2 += __ldcg(parts + (size_t)p * BH + red_off);
            a2 = tanhf(a2);
            g_hsf[(size_t)t * BH + red_off] = __float2half_rn(a2);
            if (hid_out && t == T_STEPS - 1)
                hid_out[red_off] = a2;
        }

        __threadfence();
        __syncthreads();
        if (tid == 0)
            *(volatile u32*)&g_stepf[ct][kc] = (u32)(t + 1);
    }

    // reset flags for graph replay (behind the rec grid barrier)
    grid_barrier(0);
    if (blockIdx.x == 0) {
        ((u32*)g_stepf)[tid] = 0;                  // 256 entries
    } else if (blockIdx.x == 1 && tid < 128) {
        g_acc_cnt[tid] = 0;
    }
}

// ---------------------------------------------------------------------------
// MEGA: blocks 0..255 rec, 256..1279 K1 tiles. K3 serial afterwards.
// ---------------------------------------------------------------------------
__global__ __launch_bounds__(256, 2) __cluster_dims__(KSPLIT, 1, 1)
void mega(float* __restrict__ hid_out)
{
    extern __shared__ char msm[];
    if (blockIdx.x < NREC) { rec_body(msm, hid_out); return; }
    int idx = blockIdx.x - NREC;
    gemm_body<0>(msm, idx >> 3, idx & 7, (const float*)0, (float*)0);
}

// ---------------------------------------------------------------------------
extern "C" void kernel_launch(void* const* d_in, const int* in_sizes, int n_in,
                              void* d_out, int out_size)
{
    const int*   input   = (const int*)  d_in[0];
    const float* hidden0 = (const float*)d_in[1];
    const float* emb     = (const float*)d_in[2];
    const float* Wi      = (const float*)d_in[3];
    const float* bi      = (const float*)d_in[4];
    const float* Wh      = (const float*)d_in[5];
    const float* bh      = (const float*)d_in[6];
    const float* Wo      = (const float*)d_in[7];
    const float* bo      = (const float*)d_in[8];
    float* out = (float*)d_out;

    float* hid_out = (out_size >= M_TOT * O_SZ + BH) ? out + (size_t)M_TOT * O_SZ
                                                     : (float*)0;

    cudaFuncSetAttribute(mega,     cudaFuncAttributeMaxDynamicSharedMemorySize, SMEM_MEGA);
    cudaFuncSetAttribute(gemm_out, cudaFuncAttributeMaxDynamicSharedMemorySize, SMEM_G);

    prep_bias<<<4, 256>>>(bi, bh);
    prep_transpose_f16<0><<<dim3(32, 32), 256>>>(Wi);
    prep_transpose_f16<1><<<dim3(32, 32), 256>>>(Wo);
    prep_transpose_f16<2><<<dim3(32, 32), 256>>>(Wh);
    prep_h0<<<64, 256>>>(hidden0);
    prep_gather<<<8192, 256>>>(input, emb);

    mega<<<NREC + 1024, 256, SMEM_MEGA>>>(hid_out);
    gemm_out<<<dim3(8, 128), 256, SMEM_G>>>(bo, out);
}